// round 3
// baseline (speedup 1.0000x reference)
#include <cuda_runtime.h>

typedef unsigned long long ull;

#define NPTS 65536
#define KN   32
#define NP   15
#define CIN  128
#define CM   32

// ---------------- scratch (device globals; no allocations) ----------------
__device__ float g_x1[(NPTS + 1) * CM];          // unary1 out + zero pad row
__device__ float g_rs[NPTS + 1];                 // row sums of x1 + 0 pad
__device__ float g_wf[(size_t)NPTS * NP * CM];   // wf staging (126 MB)

// ---------------- f32x2 helpers ----------------
__device__ __forceinline__ ull pack2(float lo, float hi) {
    ull r; asm("mov.b64 %0, {%1, %2};" : "=l"(r) : "f"(lo), "f"(hi)); return r;
}
__device__ __forceinline__ float2 unpack2(ull v) {
    float2 r; asm("mov.b64 {%0, %1}, %2;" : "=f"(r.x), "=f"(r.y) : "l"(v)); return r;
}
__device__ __forceinline__ void fma2(ull &d, ull a, ull b) {
    asm("fma.rn.f32x2 %0, %1, %2, %0;" : "+l"(d) : "l"(a), "l"(b));
}
__device__ __forceinline__ float sqrt_approx(float x) {
    float r; asm("sqrt.approx.f32 %0, %1;" : "=f"(r) : "f"(x)); return r;
}
__device__ __forceinline__ float lrelu(float x) { return x >= 0.f ? x : 0.1f * x; }

// =====================================================================
// K1: x1 = leaky(LN(s_feats @ w1 + b1)); emits g_rs row sums + pad row
// =====================================================================
__global__ __launch_bounds__(256) void k_unary1(
    const float* __restrict__ sf, const float* __restrict__ w1,
    const float* __restrict__ b1, const float* __restrict__ g1,
    const float* __restrict__ bb1)
{
    __shared__ __align__(16) float w1s[CIN * CM];  // 16 KB
    __shared__ float p1[96];
    int t = threadIdx.x;
#pragma unroll
    for (int i = 0; i < 16; i++) w1s[t + 256 * i] = w1[t + 256 * i];
    if (t < 32) { p1[t] = b1[t]; p1[32 + t] = g1[t]; p1[64 + t] = bb1[t]; }
    __syncthreads();

    int n = blockIdx.x * 256 + t;
    ull acc[16];
#pragma unroll
    for (int c = 0; c < 16; c++) acc[c] = pack2(p1[2 * c], p1[2 * c + 1]);

    const float4* row = reinterpret_cast<const float4*>(sf + (size_t)n * CIN);
#pragma unroll 4
    for (int i4 = 0; i4 < 32; i4++) {
        float4 x = __ldg(&row[i4]);
        const float* wr = &w1s[i4 * 4 * CM];
        ull xx;
        xx = pack2(x.x, x.x);
#pragma unroll
        for (int c = 0; c < 16; c++) fma2(acc[c], *(const ull*)&wr[2 * c], xx);
        xx = pack2(x.y, x.y);
#pragma unroll
        for (int c = 0; c < 16; c++) fma2(acc[c], *(const ull*)&wr[CM + 2 * c], xx);
        xx = pack2(x.z, x.z);
#pragma unroll
        for (int c = 0; c < 16; c++) fma2(acc[c], *(const ull*)&wr[2 * CM + 2 * c], xx);
        xx = pack2(x.w, x.w);
#pragma unroll
        for (int c = 0; c < 16; c++) fma2(acc[c], *(const ull*)&wr[3 * CM + 2 * c], xx);
    }

    float v[32], s = 0.f, ss = 0.f;
#pragma unroll
    for (int c = 0; c < 16; c++) {
        float2 u = unpack2(acc[c]);
        v[2 * c] = u.x; v[2 * c + 1] = u.y;
        s += u.x + u.y; ss += u.x * u.x + u.y * u.y;
    }
    float m = s * (1.f / 32.f);
    float rstd = rsqrtf(ss * (1.f / 32.f) - m * m + 1e-5f);

    float rsum = 0.f, y[32];
#pragma unroll
    for (int c = 0; c < 32; c++) {
        float z = lrelu((v[c] - m) * rstd * p1[32 + c] + p1[64 + c]);
        y[c] = z; rsum += z;
    }
    float4* dst = reinterpret_cast<float4*>(g_x1 + (size_t)n * CM);
#pragma unroll
    for (int q = 0; q < 8; q++)
        dst[q] = make_float4(y[4 * q], y[4 * q + 1], y[4 * q + 2], y[4 * q + 3]);
    g_rs[n] = rsum;

    if (n == 0) {  // zero pad row for shadow neighbors
        float4* pd = reinterpret_cast<float4*>(g_x1 + (size_t)NPTS * CM);
#pragma unroll
        for (int q = 0; q < 8; q++) pd[q] = make_float4(0.f, 0.f, 0.f, 0.f);
        g_rs[NPTS] = 0.f;
    }
}

// =====================================================================
// K2: wf[n,p,c] = (1/nnum) * sum_k w[n,k,p] * x1[idx_k, c]
// warp-per-point: lane=k for weights, lane=c for accumulation
// =====================================================================
__global__ __launch_bounds__(256) void k_kpconv(
    const int* __restrict__ nbr, const float* __restrict__ qp,
    const float* __restrict__ sp, const float* __restrict__ kpt)
{
    __shared__ __align__(16) float ws[8][32][20];  // stride 20: 16B-aligned rows
    __shared__ int idxs[8][32];
    __shared__ float kps[45];

    int t = threadIdx.x, wid = t >> 5, lane = t & 31;
    if (t < 45) kps[t] = kpt[t];
    __syncthreads();

    int n = blockIdx.x * 8 + wid;
    int idx = nbr[(size_t)n * KN + lane];
    bool valid = idx < NPTS;
    float px, py, pz;
    if (valid) { px = sp[idx * 3]; py = sp[idx * 3 + 1]; pz = sp[idx * 3 + 2]; }
    else       { px = py = pz = 1e6f; }
    float rx = px - qp[n * 3], ry = py - qp[n * 3 + 1], rz = pz - qp[n * 3 + 2];

    float rs = g_rs[idx];                       // pad row -> 0
    unsigned bal = __ballot_sync(0xffffffffu, rs > 0.f);
    int nnum = __popc(bal); if (nnum < 1) nnum = 1;
    float inv = 1.f / (float)nnum;

    idxs[wid][lane] = idx;
#pragma unroll
    for (int p = 0; p < NP; p++) {
        float dx = rx - kps[p * 3], dy = ry - kps[p * 3 + 1], dz = rz - kps[p * 3 + 2];
        float d2 = fmaf(dx, dx, fmaf(dy, dy, dz * dz));
        float w = fmaf(sqrt_approx(d2), -0.5f, 1.0f);
        ws[wid][lane][p] = (w > 0.f ? w : 0.f) * inv;
    }
    ws[wid][lane][15] = 0.f;
    __syncwarp();

    ull acc[8];
#pragma unroll
    for (int pp = 0; pp < 8; pp++) acc[pp] = 0ull;

    const int* myidx = idxs[wid];
#pragma unroll 4
    for (int k = 0; k < KN; k++) {
        int ik = myidx[k];
        float x = __ldg(&g_x1[(size_t)ik * CM + lane]);   // coalesced 128B row
        ull xx = pack2(x, x);
        const ulonglong2* wp = reinterpret_cast<const ulonglong2*>(&ws[wid][k][0]);
        ulonglong2 wa = wp[0], wb = wp[1], wc = wp[2], wd = wp[3];  // broadcast LDS
        fma2(acc[0], wa.x, xx); fma2(acc[1], wa.y, xx);
        fma2(acc[2], wb.x, xx); fma2(acc[3], wb.y, xx);
        fma2(acc[4], wc.x, xx); fma2(acc[5], wc.y, xx);
        fma2(acc[6], wd.x, xx); fma2(acc[7], wd.y, xx);
    }

    float* dst = g_wf + (size_t)n * (NP * CM);
#pragma unroll
    for (int pp = 0; pp < 8; pp++) {
        float2 u = unpack2(acc[pp]);
        dst[(2 * pp) * CM + lane] = u.x;
        if (pp < 7) dst[(2 * pp + 1) * CM + lane] = u.y;
    }
}

// =====================================================================
// K3: out = leaky( LN2( leaky(LN1(einsum2(wf,Wkp))) @ w2 + b2 ) + sf )
// =====================================================================
__global__ __launch_bounds__(256, 2) void k_tail(
    const float* __restrict__ kpw, const float* __restrict__ w2,
    const float* __restrict__ sf,
    const float* __restrict__ gn, const float* __restrict__ bn,
    const float* __restrict__ b2, const float* __restrict__ g2,
    const float* __restrict__ bb2, float* __restrict__ out)
{
    extern __shared__ float sm[];
    float* w2s = sm;              // 4096
    float* Wp  = sm + 4096;       // 1024
    float* wfs = sm + 5120;       // 256*33 = 8448 (conflict-free stride)
    float* par = sm + 13568;      // 448

    int t = threadIdx.x;
    int n0 = blockIdx.x * 256;
    int n = n0 + t;

#pragma unroll
    for (int i = 0; i < 16; i++) w2s[t + 256 * i] = w2[t + 256 * i];
    if (t < 32) { par[t] = gn[t]; par[32 + t] = bn[t]; }
    if (t < 128) { par[64 + t] = b2[t]; par[192 + t] = g2[t]; par[320 + t] = bb2[t]; }

    ull acc[16];
#pragma unroll
    for (int q = 0; q < 16; q++) acc[q] = 0ull;

    for (int p = 0; p < NP; p++) {
        __syncthreads();
        reinterpret_cast<float4*>(Wp)[t] =
            __ldg(reinterpret_cast<const float4*>(kpw + (size_t)p * 1024) + t);
#pragma unroll
        for (int j = 0; j < 8; j++) {
            int fi = j * 256 + t;
            int pt = fi >> 3, cq = fi & 7;
            float4 vv = __ldg(reinterpret_cast<const float4*>(
                                  g_wf + (size_t)(n0 + pt) * (NP * CM) + p * CM) + cq);
            float* d = &wfs[pt * 33 + cq * 4];
            d[0] = vv.x; d[1] = vv.y; d[2] = vv.z; d[3] = vv.w;
        }
        __syncthreads();

        const float* mywf = &wfs[t * 33];
#pragma unroll
        for (int c = 0; c < CM; c++) {
            float wv = mywf[c];
            ull ww = pack2(wv, wv);
            const ulonglong2* wr = reinterpret_cast<const ulonglong2*>(&Wp[c * 32]);
#pragma unroll
            for (int q = 0; q < 8; q++) {
                ulonglong2 u = wr[q];
                fma2(acc[2 * q], u.x, ww);
                fma2(acc[2 * q + 1], u.y, ww);
            }
        }
    }

    // LN(gn,bn) + leaky over 32 channels (in-registers)
    float v[32], s = 0.f, ssum = 0.f;
#pragma unroll
    for (int q = 0; q < 16; q++) {
        float2 u = unpack2(acc[q]);
        v[2 * q] = u.x; v[2 * q + 1] = u.y;
        s += u.x + u.y; ssum += u.x * u.x + u.y * u.y;
    }
    float m = s * (1.f / 32.f);
    float rstd = rsqrtf(ssum * (1.f / 32.f) - m * m + 1e-5f);
#pragma unroll
    for (int c = 0; c < 32; c++)
        v[c] = lrelu((v[c] - m) * rstd * par[c] + par[32 + c]);

    // unary2 in 4 chunks of 32 outputs; stash pre-LN results in d_out row
    float sum2 = 0.f, ss2 = 0.f;
    float* orow = out + (size_t)n * CIN;
#pragma unroll
    for (int ch = 0; ch < 4; ch++) {
        ull a2[16];
#pragma unroll
        for (int o = 0; o < 16; o++)
            a2[o] = pack2(par[64 + ch * 32 + 2 * o], par[64 + ch * 32 + 2 * o + 1]);
#pragma unroll
        for (int c = 0; c < 32; c++) {
            ull vv = pack2(v[c], v[c]);
            const ulonglong2* wr2 =
                reinterpret_cast<const ulonglong2*>(&w2s[c * CIN + ch * 32]);
#pragma unroll
            for (int q = 0; q < 8; q++) {
                ulonglong2 u = wr2[q];
                fma2(a2[2 * q], u.x, vv);
                fma2(a2[2 * q + 1], u.y, vv);
            }
        }
        float4* o4 = reinterpret_cast<float4*>(orow) + ch * 8;
#pragma unroll
        for (int q = 0; q < 8; q++) {
            float2 e = unpack2(a2[2 * q]);
            float2 f = unpack2(a2[2 * q + 1]);
            sum2 += e.x + e.y + f.x + f.y;
            ss2  += e.x * e.x + e.y * e.y + f.x * f.x + f.y * f.y;
            o4[q] = make_float4(e.x, e.y, f.x, f.y);
        }
    }

    // final LN(g2,bb2) + residual + leaky
    float m2 = sum2 * (1.f / 128.f);
    float rstd2 = rsqrtf(ss2 * (1.f / 128.f) - m2 * m2 + 1e-5f);
    const float4* sfr = reinterpret_cast<const float4*>(sf + (size_t)n * CIN);
    float4* o4 = reinterpret_cast<float4*>(orow);
#pragma unroll
    for (int i = 0; i < 32; i++) {
        float4 z = o4[i];
        float4 f = __ldg(&sfr[i]);
        int o = i * 4;
        z.x = lrelu((z.x - m2) * rstd2 * par[192 + o]     + par[320 + o]     + f.x);
        z.y = lrelu((z.y - m2) * rstd2 * par[192 + o + 1] + par[320 + o + 1] + f.y);
        z.z = lrelu((z.z - m2) * rstd2 * par[192 + o + 2] + par[320 + o + 2] + f.z);
        z.w = lrelu((z.w - m2) * rstd2 * par[192 + o + 3] + par[320 + o + 3] + f.w);
        o4[i] = z;
    }
}

// =====================================================================
extern "C" void kernel_launch(void* const* d_in, const int* in_sizes, int n_in,
                              void* d_out, int out_size)
{
    (void)in_sizes; (void)n_in; (void)out_size;
    const float* sf  = (const float*)d_in[0];
    const float* qp  = (const float*)d_in[1];
    const float* sp  = (const float*)d_in[2];
    const int*   nbr = (const int*)  d_in[3];
    const float* w1  = (const float*)d_in[4];
    const float* b1  = (const float*)d_in[5];
    const float* g1  = (const float*)d_in[6];
    const float* bb1 = (const float*)d_in[7];
    const float* kpw = (const float*)d_in[8];
    const float* kpt = (const float*)d_in[9];
    const float* gn  = (const float*)d_in[10];
    const float* bn  = (const float*)d_in[11];
    const float* w2  = (const float*)d_in[12];
    const float* b2  = (const float*)d_in[13];
    const float* g2  = (const float*)d_in[14];
    const float* bb2 = (const float*)d_in[15];
    float* out = (float*)d_out;

    static int smem_set = 0;
    if (!smem_set) {
        cudaFuncSetAttribute(k_tail, cudaFuncAttributeMaxDynamicSharedMemorySize,
                             14016 * (int)sizeof(float));
        smem_set = 1;
    }

    k_unary1<<<NPTS / 256, 256>>>(sf, w1, b1, g1, bb1);
    k_kpconv<<<NPTS / 8, 256>>>(nbr, qp, sp, kpt);
    k_tail<<<NPTS / 256, 256, 14016 * sizeof(float)>>>(
        kpw, w2, sf, gn, bn, b2, g2, bb2, out);
}

// round 6
// speedup vs baseline: 1.0003x; 1.0003x over previous
#include <cuda_runtime.h>

typedef unsigned long long ull;

#define NPTS 65536
#define KN   32
#define NP   15
#define CIN  128
#define CM   32

// ---------------- scratch (device globals; no allocations) ----------------
__device__ float g_x1[(NPTS + 1) * CM];          // unary1 out + zero pad row
__device__ float g_rs[NPTS + 1];                 // row sums of x1 + 0 pad
__device__ float g_wf[(size_t)NPTS * NP * CM];   // wf staging (126 MB)

// ---------------- f32x2 helpers ----------------
__device__ __forceinline__ ull pack2(float lo, float hi) {
    ull r; asm("mov.b64 %0, {%1, %2};" : "=l"(r) : "f"(lo), "f"(hi)); return r;
}
__device__ __forceinline__ float2 unpack2(ull v) {
    float2 r; asm("mov.b64 {%0, %1}, %2;" : "=f"(r.x), "=f"(r.y) : "l"(v)); return r;
}
__device__ __forceinline__ void fma2(ull &d, ull a, ull b) {
    asm("fma.rn.f32x2 %0, %1, %2, %0;" : "+l"(d) : "l"(a), "l"(b));
}
__device__ __forceinline__ float sqrt_approx(float x) {
    float r; asm("sqrt.approx.f32 %0, %1;" : "=f"(r) : "f"(x)); return r;
}
__device__ __forceinline__ float lrelu(float x) { return x >= 0.f ? x : 0.1f * x; }

// =====================================================================
// K1: x1 = leaky(LN(s_feats @ w1 + b1)); emits g_rs row sums + pad row
// 128 threads, 2 points/thread, 256 points/block, smem-staged input
// =====================================================================
__device__ __forceinline__ void u1_epilogue(
    ull (&acc)[16], const float* __restrict__ p1, int n)
{
    float v[32], s = 0.f, ss = 0.f;
#pragma unroll
    for (int c = 0; c < 16; c++) {
        float2 u = unpack2(acc[c]);
        u.x += p1[2 * c]; u.y += p1[2 * c + 1];
        v[2 * c] = u.x; v[2 * c + 1] = u.y;
        s += u.x + u.y; ss += u.x * u.x + u.y * u.y;
    }
    float m = s * (1.f / 32.f);
    float rstd = rsqrtf(ss * (1.f / 32.f) - m * m + 1e-5f);
    float rsum = 0.f;
#pragma unroll
    for (int c = 0; c < 32; c++) {
        float z = lrelu((v[c] - m) * rstd * p1[32 + c] + p1[64 + c]);
        v[c] = z; rsum += z;
    }
    float4* dst = reinterpret_cast<float4*>(g_x1 + (size_t)n * CM);
#pragma unroll
    for (int q = 0; q < 8; q++)
        dst[q] = make_float4(v[4 * q], v[4 * q + 1], v[4 * q + 2], v[4 * q + 3]);
    g_rs[n] = rsum;
}

__global__ __launch_bounds__(128) void k_unary1(
    const float* __restrict__ sf, const float* __restrict__ w1,
    const float* __restrict__ b1, const float* __restrict__ g1,
    const float* __restrict__ bb1)
{
    extern __shared__ float sm1[];
    float* w1s = sm1;            // 4096 floats (16 KB)
    float* xs  = sm1 + 4096;     // 256*33 floats (33.8 KB, padded stride)
    __shared__ float p1[96];

    int t = threadIdx.x;
    int n0 = blockIdx.x * 256;

#pragma unroll
    for (int i = 0; i < 8; i++)
        reinterpret_cast<float4*>(w1s)[t + 128 * i] =
            __ldg(reinterpret_cast<const float4*>(w1) + t + 128 * i);
    if (t < 32) { p1[t] = b1[t]; p1[32 + t] = g1[t]; p1[64 + t] = bb1[t]; }

    ull acc0[16], acc1[16];
#pragma unroll
    for (int c = 0; c < 16; c++) { acc0[c] = 0ull; acc1[c] = 0ull; }

    for (int ch = 0; ch < 4; ch++) {
        if (ch > 0) __syncthreads();   // WAR on xs
#pragma unroll
        for (int j = 0; j < 16; j++) {
            int fi = j * 128 + t;
            int row = fi >> 3, q = fi & 7;
            float4 v = __ldg(reinterpret_cast<const float4*>(
                                 sf + (size_t)(n0 + row) * CIN + ch * 32) + q);
            float* d = &xs[row * 33 + q * 4];
            d[0] = v.x; d[1] = v.y; d[2] = v.z; d[3] = v.w;
        }
        __syncthreads();

#pragma unroll
        for (int kk = 0; kk < 32; kk++) {
            const float* wr = &w1s[(ch * 32 + kk) * CM];
            float x0 = xs[t * 33 + kk];
            float x1v = xs[(t + 128) * 33 + kk];
            ull xx0 = pack2(x0, x0), xx1 = pack2(x1v, x1v);
#pragma unroll
            for (int c = 0; c < 16; c++) {
                ull w = *(const ull*)&wr[2 * c];
                fma2(acc0[c], w, xx0);
                fma2(acc1[c], w, xx1);
            }
        }
    }

    u1_epilogue(acc0, p1, n0 + t);
    u1_epilogue(acc1, p1, n0 + t + 128);

    if (blockIdx.x == 0 && t == 0) {   // zero pad row for shadow neighbors
        float4* pd = reinterpret_cast<float4*>(g_x1 + (size_t)NPTS * CM);
#pragma unroll
        for (int q = 0; q < 8; q++) pd[q] = make_float4(0.f, 0.f, 0.f, 0.f);
        g_rs[NPTS] = 0.f;
    }
}

// =====================================================================
// K2: wf[n,p,c] = (1/nnum) * sum_k w[n,k,p] * x1[idx_k, c]
// warp-per-point: lane=k for weights, lane=c for accumulation; full
// k-unroll with shfl so gather indices are register-resident (high MLP)
// =====================================================================
__global__ __launch_bounds__(256) void k_kpconv(
    const int* __restrict__ nbr, const float* __restrict__ qp,
    const float* __restrict__ sp, const float* __restrict__ kpt)
{
    __shared__ __align__(16) float ws[8][32][20];  // 16B-aligned rows
    __shared__ float kps[45];

    int t = threadIdx.x, wid = t >> 5, lane = t & 31;
    if (t < 45) kps[t] = kpt[t];
    __syncthreads();

    int n = blockIdx.x * 8 + wid;
    int idx = nbr[(size_t)n * KN + lane];
    bool valid = idx < NPTS;
    float px, py, pz;
    if (valid) { px = sp[idx * 3]; py = sp[idx * 3 + 1]; pz = sp[idx * 3 + 2]; }
    else       { px = py = pz = 1e6f; }
    float rx = px - qp[n * 3], ry = py - qp[n * 3 + 1], rz = pz - qp[n * 3 + 2];

    float rs = g_rs[idx];                       // pad row -> 0
    unsigned bal = __ballot_sync(0xffffffffu, rs > 0.f);
    int nnum = __popc(bal); if (nnum < 1) nnum = 1;
    float inv = 1.f / (float)nnum;

#pragma unroll
    for (int p = 0; p < NP; p++) {
        float dx = rx - kps[p * 3], dy = ry - kps[p * 3 + 1], dz = rz - kps[p * 3 + 2];
        float d2 = fmaf(dx, dx, fmaf(dy, dy, dz * dz));
        float w = fmaf(sqrt_approx(d2), -0.5f, 1.0f);
        ws[wid][lane][p] = (w > 0.f ? w : 0.f) * inv;
    }
    ws[wid][lane][15] = 0.f;
    __syncwarp();

    ull acc[8];
#pragma unroll
    for (int pp = 0; pp < 8; pp++) acc[pp] = 0ull;

#pragma unroll
    for (int k = 0; k < KN; k++) {
        int ik = __shfl_sync(0xffffffffu, idx, k);
        float x = __ldg(&g_x1[(size_t)ik * CM + lane]);   // coalesced 128B row
        ull xx = pack2(x, x);
        const ulonglong2* wp = reinterpret_cast<const ulonglong2*>(&ws[wid][k][0]);
        ulonglong2 wa = wp[0], wb = wp[1], wc = wp[2], wd = wp[3];  // broadcast LDS
        fma2(acc[0], wa.x, xx); fma2(acc[1], wa.y, xx);
        fma2(acc[2], wb.x, xx); fma2(acc[3], wb.y, xx);
        fma2(acc[4], wc.x, xx); fma2(acc[5], wc.y, xx);
        fma2(acc[6], wd.x, xx); fma2(acc[7], wd.y, xx);
    }

    float* dst = g_wf + (size_t)n * (NP * CM);
#pragma unroll
    for (int pp = 0; pp < 8; pp++) {
        float2 u = unpack2(acc[pp]);
        dst[(2 * pp) * CM + lane] = u.x;
        if (pp < 7) dst[(2 * pp + 1) * CM + lane] = u.y;
    }
}

// =====================================================================
// K3: out = leaky( LN2( leaky(LN1(einsum2(wf,Wkp))) @ w2 + b2 ) + sf )
// 128 threads, 2 points/thread, 256 points/block
// =====================================================================
__device__ __forceinline__ void k3_epilogue(
    ull (&acc)[16], const float* __restrict__ par,
    const float* __restrict__ w2s, const float* __restrict__ sf,
    float* __restrict__ out, int n)
{
    // LN(gn,bn) + leaky over 32 channels (in-registers)
    float v[32], s = 0.f, ssum = 0.f;
#pragma unroll
    for (int q = 0; q < 16; q++) {
        float2 u = unpack2(acc[q]);
        v[2 * q] = u.x; v[2 * q + 1] = u.y;
        s += u.x + u.y; ssum += u.x * u.x + u.y * u.y;
    }
    float m = s * (1.f / 32.f);
    float rstd = rsqrtf(ssum * (1.f / 32.f) - m * m + 1e-5f);
#pragma unroll
    for (int c = 0; c < 32; c++)
        v[c] = lrelu((v[c] - m) * rstd * par[c] + par[32 + c]);

    // unary2 in 4 chunks of 32 outputs; stash pre-LN results in d_out row
    float sum2 = 0.f, ss2 = 0.f;
    float* orow = out + (size_t)n * CIN;
#pragma unroll
    for (int ch = 0; ch < 4; ch++) {
        ull a2[16];
#pragma unroll
        for (int o = 0; o < 16; o++)
            a2[o] = pack2(par[64 + ch * 32 + 2 * o], par[64 + ch * 32 + 2 * o + 1]);
#pragma unroll
        for (int c = 0; c < 32; c++) {
            ull vv = pack2(v[c], v[c]);
            const ulonglong2* wr2 =
                reinterpret_cast<const ulonglong2*>(&w2s[c * CIN + ch * 32]);
#pragma unroll
            for (int q = 0; q < 8; q++) {
                ulonglong2 u = wr2[q];
                fma2(a2[2 * q], u.x, vv);
                fma2(a2[2 * q + 1], u.y, vv);
            }
        }
        float4* o4 = reinterpret_cast<float4*>(orow) + ch * 8;
#pragma unroll
        for (int q = 0; q < 8; q++) {
            float2 e = unpack2(a2[2 * q]);
            float2 f = unpack2(a2[2 * q + 1]);
            sum2 += e.x + e.y + f.x + f.y;
            ss2  += e.x * e.x + e.y * e.y + f.x * f.x + f.y * f.y;
            o4[q] = make_float4(e.x, e.y, f.x, f.y);
        }
    }

    // final LN(g2,bb2) + residual + leaky
    float m2 = sum2 * (1.f / 128.f);
    float rstd2 = rsqrtf(ss2 * (1.f / 128.f) - m2 * m2 + 1e-5f);
    const float4* sfr = reinterpret_cast<const float4*>(sf + (size_t)n * CIN);
    float4* o4 = reinterpret_cast<float4*>(orow);
#pragma unroll
    for (int i = 0; i < 32; i++) {
        float4 z = o4[i];
        float4 f = __ldg(&sfr[i]);
        int o = i * 4;
        z.x = lrelu((z.x - m2) * rstd2 * par[192 + o]     + par[320 + o]     + f.x);
        z.y = lrelu((z.y - m2) * rstd2 * par[192 + o + 1] + par[320 + o + 1] + f.y);
        z.z = lrelu((z.z - m2) * rstd2 * par[192 + o + 2] + par[320 + o + 2] + f.z);
        z.w = lrelu((z.w - m2) * rstd2 * par[192 + o + 3] + par[320 + o + 3] + f.w);
        o4[i] = z;
    }
}

__global__ __launch_bounds__(128) void k_tail(
    const float* __restrict__ kpw, const float* __restrict__ w2,
    const float* __restrict__ sf,
    const float* __restrict__ gn, const float* __restrict__ bn,
    const float* __restrict__ b2, const float* __restrict__ g2,
    const float* __restrict__ bb2, float* __restrict__ out)
{
    extern __shared__ float sm[];
    float* w2s = sm;              // 4096
    float* Wp  = sm + 4096;       // 1024
    float* wfs = sm + 5120;       // 256*33 = 8448 (conflict-free stride)
    float* par = sm + 13568;      // 448

    int t = threadIdx.x;
    int n0 = blockIdx.x * 256;

#pragma unroll
    for (int i = 0; i < 8; i++)
        reinterpret_cast<float4*>(w2s)[t + 128 * i] =
            __ldg(reinterpret_cast<const float4*>(w2) + t + 128 * i);
    if (t < 32) { par[t] = gn[t]; par[32 + t] = bn[t]; }
    par[64 + t] = b2[t]; par[192 + t] = g2[t]; par[320 + t] = bb2[t];

    ull acc0[16], acc1[16];
#pragma unroll
    for (int q = 0; q < 16; q++) { acc0[q] = 0ull; acc1[q] = 0ull; }

    for (int p = 0; p < NP; p++) {
        __syncthreads();   // WAR on Wp/wfs (first iter: covers w2s/par staging)
        reinterpret_cast<float4*>(Wp)[t] =
            __ldg(reinterpret_cast<const float4*>(kpw + (size_t)p * 1024) + t);
        reinterpret_cast<float4*>(Wp)[t + 128] =
            __ldg(reinterpret_cast<const float4*>(kpw + (size_t)p * 1024) + t + 128);
#pragma unroll
        for (int j = 0; j < 16; j++) {
            int fi = j * 128 + t;
            int pt = fi >> 3, q = fi & 7;
            float4 vv = __ldg(reinterpret_cast<const float4*>(
                                  g_wf + (size_t)(n0 + pt) * (NP * CM) + p * CM) + q);
            float* d = &wfs[pt * 33 + q * 4];
            d[0] = vv.x; d[1] = vv.y; d[2] = vv.z; d[3] = vv.w;
        }
        __syncthreads();

#pragma unroll
        for (int c = 0; c < CM; c++) {
            float wv0 = wfs[t * 33 + c];
            float wv1 = wfs[(t + 128) * 33 + c];
            ull ww0 = pack2(wv0, wv0), ww1 = pack2(wv1, wv1);
            const ulonglong2* wr = reinterpret_cast<const ulonglong2*>(&Wp[c * 32]);
#pragma unroll
            for (int q = 0; q < 8; q++) {
                ulonglong2 u = wr[q];
                fma2(acc0[2 * q], u.x, ww0);
                fma2(acc0[2 * q + 1], u.y, ww0);
                fma2(acc1[2 * q], u.x, ww1);
                fma2(acc1[2 * q + 1], u.y, ww1);
            }
        }
    }

    k3_epilogue(acc0, par, w2s, sf, out, n0 + t);
    k3_epilogue(acc1, par, w2s, sf, out, n0 + t + 128);
}

// =====================================================================
extern "C" void kernel_launch(void* const* d_in, const int* in_sizes, int n_in,
                              void* d_out, int out_size)
{
    (void)in_sizes; (void)n_in; (void)out_size;
    const float* sf  = (const float*)d_in[0];
    const float* qp  = (const float*)d_in[1];
    const float* sp  = (const float*)d_in[2];
    const int*   nbr = (const int*)  d_in[3];
    const float* w1  = (const float*)d_in[4];
    const float* b1  = (const float*)d_in[5];
    const float* g1  = (const float*)d_in[6];
    const float* bb1 = (const float*)d_in[7];
    const float* kpw = (const float*)d_in[8];
    const float* kpt = (const float*)d_in[9];
    const float* gn  = (const float*)d_in[10];
    const float* bn  = (const float*)d_in[11];
    const float* w2  = (const float*)d_in[12];
    const float* b2  = (const float*)d_in[13];
    const float* g2  = (const float*)d_in[14];
    const float* bb2 = (const float*)d_in[15];
    float* out = (float*)d_out;

    const int smem1 = (4096 + 256 * 33) * (int)sizeof(float);   // 50.4 KB
    const int smem3 = 14016 * (int)sizeof(float);               // 54.8 KB
    cudaFuncSetAttribute(k_unary1, cudaFuncAttributeMaxDynamicSharedMemorySize, smem1);
    cudaFuncSetAttribute(k_tail, cudaFuncAttributeMaxDynamicSharedMemorySize, smem3);

    k_unary1<<<NPTS / 256, 128, smem1>>>(sf, w1, b1, g1, bb1);
    k_kpconv<<<NPTS / 8, 256>>>(nbr, qp, sp, kpt);
    k_tail<<<NPTS / 256, 128, smem3>>>(kpw, w2, sf, gn, bn, b2, g2, bb2, out);
}

// round 7
// speedup vs baseline: 1.1066x; 1.1063x over previous
#include <cuda_runtime.h>
#include <cuda_fp16.h>

typedef unsigned long long ull;

#define NPTS 65536
#define KN   32
#define NP   15
#define CIN  128
#define CM   32

// ---------------- scratch (device globals; no allocations) ----------------
__device__ float g_x1[(NPTS + 1) * CM];              // unary1 out + zero pad row
__device__ float g_rs[NPTS + 1];                     // row sums of x1 + 0 pad
__device__ __half g_wf_h[(size_t)NP * NPTS * CM];    // wf staging, fp16, [p][n][c] (63 MB)

// ---------------- f32x2 helpers ----------------
__device__ __forceinline__ ull pack2(float lo, float hi) {
    ull r; asm("mov.b64 %0, {%1, %2};" : "=l"(r) : "f"(lo), "f"(hi)); return r;
}
__device__ __forceinline__ float2 unpack2(ull v) {
    float2 r; asm("mov.b64 {%0, %1}, %2;" : "=f"(r.x), "=f"(r.y) : "l"(v)); return r;
}
__device__ __forceinline__ void fma2(ull &d, ull a, ull b) {
    asm("fma.rn.f32x2 %0, %1, %2, %0;" : "+l"(d) : "l"(a), "l"(b));
}
__device__ __forceinline__ float sqrt_approx(float x) {
    float r; asm("sqrt.approx.f32 %0, %1;" : "=f"(r) : "f"(x)); return r;
}
__device__ __forceinline__ float lrelu(float x) { return x >= 0.f ? x : 0.1f * x; }

// =====================================================================
// K1: x1 = leaky(LN(s_feats @ w1 + b1)); emits g_rs row sums + pad row
// 128 threads, 2 points/thread, 256 points/block, smem-staged input
// =====================================================================
__device__ __forceinline__ void u1_epilogue(
    ull (&acc)[16], const float* __restrict__ p1, int n)
{
    float v[32], s = 0.f, ss = 0.f;
#pragma unroll
    for (int c = 0; c < 16; c++) {
        float2 u = unpack2(acc[c]);
        u.x += p1[2 * c]; u.y += p1[2 * c + 1];
        v[2 * c] = u.x; v[2 * c + 1] = u.y;
        s += u.x + u.y; ss += u.x * u.x + u.y * u.y;
    }
    float m = s * (1.f / 32.f);
    float rstd = rsqrtf(ss * (1.f / 32.f) - m * m + 1e-5f);
    float rsum = 0.f;
#pragma unroll
    for (int c = 0; c < 32; c++) {
        float z = lrelu((v[c] - m) * rstd * p1[32 + c] + p1[64 + c]);
        v[c] = z; rsum += z;
    }
    float4* dst = reinterpret_cast<float4*>(g_x1 + (size_t)n * CM);
#pragma unroll
    for (int q = 0; q < 8; q++)
        dst[q] = make_float4(v[4 * q], v[4 * q + 1], v[4 * q + 2], v[4 * q + 3]);
    g_rs[n] = rsum;
}

__global__ __launch_bounds__(128) void k_unary1(
    const float* __restrict__ sf, const float* __restrict__ w1,
    const float* __restrict__ b1, const float* __restrict__ g1,
    const float* __restrict__ bb1)
{
    extern __shared__ float sm1[];
    float* w1s = sm1;            // 4096 floats (16 KB)
    float* xs  = sm1 + 4096;     // 256*33 floats (33.8 KB, padded stride)
    __shared__ float p1[96];

    int t = threadIdx.x;
    int n0 = blockIdx.x * 256;

#pragma unroll
    for (int i = 0; i < 8; i++)
        reinterpret_cast<float4*>(w1s)[t + 128 * i] =
            __ldg(reinterpret_cast<const float4*>(w1) + t + 128 * i);
    if (t < 32) { p1[t] = b1[t]; p1[32 + t] = g1[t]; p1[64 + t] = bb1[t]; }

    ull acc0[16], acc1[16];
#pragma unroll
    for (int c = 0; c < 16; c++) { acc0[c] = 0ull; acc1[c] = 0ull; }

    for (int ch = 0; ch < 4; ch++) {
        if (ch > 0) __syncthreads();   // WAR on xs
#pragma unroll
        for (int j = 0; j < 16; j++) {
            int fi = j * 128 + t;
            int row = fi >> 3, q = fi & 7;
            float4 v = __ldg(reinterpret_cast<const float4*>(
                                 sf + (size_t)(n0 + row) * CIN + ch * 32) + q);
            float* d = &xs[row * 33 + q * 4];
            d[0] = v.x; d[1] = v.y; d[2] = v.z; d[3] = v.w;
        }
        __syncthreads();

#pragma unroll
        for (int kk = 0; kk < 32; kk++) {
            const float* wr = &w1s[(ch * 32 + kk) * CM];
            float x0 = xs[t * 33 + kk];
            float x1v = xs[(t + 128) * 33 + kk];
            ull xx0 = pack2(x0, x0), xx1 = pack2(x1v, x1v);
#pragma unroll
            for (int c = 0; c < 16; c++) {
                ull w = *(const ull*)&wr[2 * c];
                fma2(acc0[c], w, xx0);
                fma2(acc1[c], w, xx1);
            }
        }
    }

    u1_epilogue(acc0, p1, n0 + t);
    u1_epilogue(acc1, p1, n0 + t + 128);

    if (blockIdx.x == 0 && t == 0) {   // zero pad row for shadow neighbors
        float4* pd = reinterpret_cast<float4*>(g_x1 + (size_t)NPTS * CM);
#pragma unroll
        for (int q = 0; q < 8; q++) pd[q] = make_float4(0.f, 0.f, 0.f, 0.f);
        g_rs[NPTS] = 0.f;
    }
}

// =====================================================================
// K2: wf[p][n][c] (fp16) = (1/nnum) * sum_k w[n,k,p] * x1[idx_k, c]
// warp-per-point: lane=k for weights, lane=c for accumulation
// =====================================================================
__global__ __launch_bounds__(256) void k_kpconv(
    const int* __restrict__ nbr, const float* __restrict__ qp,
    const float* __restrict__ sp, const float* __restrict__ kpt)
{
    __shared__ __align__(16) float ws[8][32][20];  // 16B-aligned rows
    __shared__ float kps[45];

    int t = threadIdx.x, wid = t >> 5, lane = t & 31;
    if (t < 45) kps[t] = kpt[t];
    __syncthreads();

    int n = blockIdx.x * 8 + wid;
    int idx = nbr[(size_t)n * KN + lane];
    bool valid = idx < NPTS;
    float px, py, pz;
    if (valid) { px = sp[idx * 3]; py = sp[idx * 3 + 1]; pz = sp[idx * 3 + 2]; }
    else       { px = py = pz = 1e6f; }
    float rx = px - qp[n * 3], ry = py - qp[n * 3 + 1], rz = pz - qp[n * 3 + 2];

    float rs = g_rs[idx];                       // pad row -> 0
    unsigned bal = __ballot_sync(0xffffffffu, rs > 0.f);
    int nnum = __popc(bal); if (nnum < 1) nnum = 1;
    float inv = 1.f / (float)nnum;

#pragma unroll
    for (int p = 0; p < NP; p++) {
        float dx = rx - kps[p * 3], dy = ry - kps[p * 3 + 1], dz = rz - kps[p * 3 + 2];
        float d2 = fmaf(dx, dx, fmaf(dy, dy, dz * dz));
        float w = fmaf(sqrt_approx(d2), -0.5f, 1.0f);
        ws[wid][lane][p] = (w > 0.f ? w : 0.f) * inv;
    }
    ws[wid][lane][15] = 0.f;
    __syncwarp();

    ull acc[8];
#pragma unroll
    for (int pp = 0; pp < 8; pp++) acc[pp] = 0ull;

#pragma unroll
    for (int k = 0; k < KN; k++) {
        int ik = __shfl_sync(0xffffffffu, idx, k);
        float x = __ldg(&g_x1[(size_t)ik * CM + lane]);   // coalesced 128B row
        ull xx = pack2(x, x);
        const ulonglong2* wp = reinterpret_cast<const ulonglong2*>(&ws[wid][k][0]);
        ulonglong2 wa = wp[0], wb = wp[1], wc = wp[2], wd = wp[3];  // broadcast LDS
        fma2(acc[0], wa.x, xx); fma2(acc[1], wa.y, xx);
        fma2(acc[2], wb.x, xx); fma2(acc[3], wb.y, xx);
        fma2(acc[4], wc.x, xx); fma2(acc[5], wc.y, xx);
        fma2(acc[6], wd.x, xx); fma2(acc[7], wd.y, xx);
    }

    // store fp16, [p][n][c] layout (coalesced 64B warp-stores)
#pragma unroll
    for (int pp = 0; pp < 8; pp++) {
        float2 u = unpack2(acc[pp]);
        g_wf_h[((size_t)(2 * pp) * NPTS + n) * CM + lane] = __float2half(u.x);
        if (pp < 7)
            g_wf_h[((size_t)(2 * pp + 1) * NPTS + n) * CM + lane] = __float2half(u.y);
    }
}

// =====================================================================
// K3: out = leaky( LN2( leaky(LN1(einsum2(wf,Wkp))) @ w2 + b2 ) + sf )
// 128 threads, 1 point/thread, 128 points/block, 512 blocks
// single-pass: all 128 unary2 outputs held in registers
// =====================================================================
__global__ __launch_bounds__(128) void k_tail(
    const float* __restrict__ kpw, const float* __restrict__ w2,
    const float* __restrict__ sf,
    const float* __restrict__ gn, const float* __restrict__ bn,
    const float* __restrict__ b2, const float* __restrict__ g2,
    const float* __restrict__ bb2, float* __restrict__ out)
{
    extern __shared__ float sm[];
    float* w2s = sm;              // 4096
    float* Wp  = sm + 4096;       // 1024
    float* wfs = sm + 5120;       // 128*33 = 4224 (conflict-free stride)
    float* par = sm + 9344;       // 448

    int t = threadIdx.x;
    int n0 = blockIdx.x * 128;
    int n = n0 + t;

#pragma unroll
    for (int i = 0; i < 8; i++)
        reinterpret_cast<float4*>(w2s)[t + 128 * i] =
            __ldg(reinterpret_cast<const float4*>(w2) + t + 128 * i);
    if (t < 32) { par[t] = gn[t]; par[32 + t] = bn[t]; }
    par[64 + t] = b2[t]; par[192 + t] = g2[t]; par[320 + t] = bb2[t];

    ull acc[16];
#pragma unroll
    for (int q = 0; q < 16; q++) acc[q] = 0ull;

    for (int p = 0; p < NP; p++) {
        __syncthreads();   // WAR on Wp/wfs (first iter: covers w2s/par staging)
        reinterpret_cast<float4*>(Wp)[t] =
            __ldg(reinterpret_cast<const float4*>(kpw + (size_t)p * 1024) + t);
        reinterpret_cast<float4*>(Wp)[t + 128] =
            __ldg(reinterpret_cast<const float4*>(kpw + (size_t)p * 1024) + t + 128);
        // stage wf tile: 128 rows x 32 half = 8 KB contiguous, fully coalesced
        const uint4* src = reinterpret_cast<const uint4*>(
            g_wf_h + ((size_t)p * NPTS + n0) * CM);
#pragma unroll
        for (int j = 0; j < 4; j++) {
            int u = j * 128 + t;
            uint4 hv = __ldg(&src[u]);
            int pt = u >> 2, coff = (u & 3) * 8;
            const __half2* hp = reinterpret_cast<const __half2*>(&hv);
            float* d = &wfs[pt * 33 + coff];
#pragma unroll
            for (int i = 0; i < 4; i++) {
                float2 f = __half22float2(hp[i]);
                d[2 * i] = f.x; d[2 * i + 1] = f.y;
            }
        }
        __syncthreads();

#pragma unroll
        for (int c = 0; c < CM; c++) {
            float wv = wfs[t * 33 + c];
            ull ww = pack2(wv, wv);
            const ulonglong2* wr = reinterpret_cast<const ulonglong2*>(&Wp[c * 32]);
#pragma unroll
            for (int q = 0; q < 8; q++) {
                ulonglong2 u = wr[q];
                fma2(acc[2 * q], u.x, ww);
                fma2(acc[2 * q + 1], u.y, ww);
            }
        }
    }

    // LN(gn,bn) + leaky over 32 channels (in-registers)
    float v[32], s = 0.f, ssum = 0.f;
#pragma unroll
    for (int q = 0; q < 16; q++) {
        float2 u = unpack2(acc[q]);
        v[2 * q] = u.x; v[2 * q + 1] = u.y;
        s += u.x + u.y; ssum += u.x * u.x + u.y * u.y;
    }
    float m = s * (1.f / 32.f);
    float rstd = rsqrtf(ssum * (1.f / 32.f) - m * m + 1e-5f);
#pragma unroll
    for (int c = 0; c < 32; c++)
        v[c] = lrelu((v[c] - m) * rstd * par[c] + par[32 + c]);

    // unary2: all 128 outputs in registers (64 ull), single pass
    ull aa[64];
    float sum2 = 0.f, ss2 = 0.f;
#pragma unroll
    for (int ch = 0; ch < 4; ch++) {
#pragma unroll
        for (int o = 0; o < 16; o++)
            aa[ch * 16 + o] =
                pack2(par[64 + ch * 32 + 2 * o], par[64 + ch * 32 + 2 * o + 1]);
#pragma unroll
        for (int c = 0; c < 32; c++) {
            ull vv = pack2(v[c], v[c]);
            const ulonglong2* wr2 =
                reinterpret_cast<const ulonglong2*>(&w2s[c * CIN + ch * 32]);
#pragma unroll
            for (int q = 0; q < 8; q++) {
                ulonglong2 u = wr2[q];
                fma2(aa[ch * 16 + 2 * q], u.x, vv);
                fma2(aa[ch * 16 + 2 * q + 1], u.y, vv);
            }
        }
    }
#pragma unroll
    for (int j = 0; j < 64; j++) {
        float2 u = unpack2(aa[j]);
        sum2 += u.x + u.y;
        ss2  += u.x * u.x + u.y * u.y;
    }

    // final LN(g2,bb2) + residual + leaky, single store pass
    float m2 = sum2 * (1.f / 128.f);
    float rstd2 = rsqrtf(ss2 * (1.f / 128.f) - m2 * m2 + 1e-5f);
    const float4* sfr = reinterpret_cast<const float4*>(sf + (size_t)n * CIN);
    float4* o4 = reinterpret_cast<float4*>(out + (size_t)n * CIN);
#pragma unroll
    for (int i = 0; i < 32; i++) {
        float2 e = unpack2(aa[2 * i]);
        float2 fpair = unpack2(aa[2 * i + 1]);
        float4 f = __ldg(&sfr[i]);
        int o = i * 4;
        float4 z;
        z.x = lrelu((e.x - m2) * rstd2 * par[192 + o]     + par[320 + o]     + f.x);
        z.y = lrelu((e.y - m2) * rstd2 * par[192 + o + 1] + par[320 + o + 1] + f.y);
        z.z = lrelu((fpair.x - m2) * rstd2 * par[192 + o + 2] + par[320 + o + 2] + f.z);
        z.w = lrelu((fpair.y - m2) * rstd2 * par[192 + o + 3] + par[320 + o + 3] + f.w);
        o4[i] = z;
    }
}

// =====================================================================
extern "C" void kernel_launch(void* const* d_in, const int* in_sizes, int n_in,
                              void* d_out, int out_size)
{
    (void)in_sizes; (void)n_in; (void)out_size;
    const float* sf  = (const float*)d_in[0];
    const float* qp  = (const float*)d_in[1];
    const float* sp  = (const float*)d_in[2];
    const int*   nbr = (const int*)  d_in[3];
    const float* w1  = (const float*)d_in[4];
    const float* b1  = (const float*)d_in[5];
    const float* g1  = (const float*)d_in[6];
    const float* bb1 = (const float*)d_in[7];
    const float* kpw = (const float*)d_in[8];
    const float* kpt = (const float*)d_in[9];
    const float* gn  = (const float*)d_in[10];
    const float* bn  = (const float*)d_in[11];
    const float* w2  = (const float*)d_in[12];
    const float* b2  = (const float*)d_in[13];
    const float* g2  = (const float*)d_in[14];
    const float* bb2 = (const float*)d_in[15];
    float* out = (float*)d_out;

    const int smem1 = (4096 + 256 * 33) * (int)sizeof(float);   // 50.4 KB
    const int smem3 = 9792 * (int)sizeof(float);                // 39.2 KB
    cudaFuncSetAttribute(k_unary1, cudaFuncAttributeMaxDynamicSharedMemorySize, smem1);
    cudaFuncSetAttribute(k_tail, cudaFuncAttributeMaxDynamicSharedMemorySize, smem3);

    k_unary1<<<NPTS / 256, 128, smem1>>>(sf, w1, b1, g1, bb1);
    k_kpconv<<<NPTS / 8, 256>>>(nbr, qp, sp, kpt);
    k_tail<<<NPTS / 128, 128, smem3>>>(kpw, w2, sf, gn, bn, b2, g2, bb2, out);
}